// round 16
// baseline (speedup 1.0000x reference)
#include <cuda_runtime.h>
#include <cuda_bf16.h>
#include <cstdint>

#define BB 16
#define SS 128
#define TT 64
#define EE 768
#define HH 1024
#define VV 32000

// ---------------- device scratch (static, no allocation) ----------------
__device__ __nv_bfloat16 g_xbf[BB * SS * EE];
__device__ __nv_bfloat16 g_xprojbf[BB * SS * HH];
__device__ uint4 g_pWx[(HH / 16) * (EE / 16) * 32];
__device__ uint4 g_pWh[(HH / 16) * (HH / 16) * 32];
__device__ uint4 g_pWc0[(4096 / 16) * (2560 / 16) * 32];
__device__ uint4 g_pWc1[(4096 / 16) * (2048 / 16) * 32];
__device__ uint4 g_pWc2[(4096 / 16) * (2048 / 16) * 32];
__device__ uint4 g_pFc[(VV / 16) * (HH / 16) * 32];

__device__ __nv_bfloat16 g_A0[BB * 2560];        // [emb | ctx | h0]
__device__ __nv_bfloat16 g_A1[BB * 2048];        // [h0 | h1_prev]
__device__ __nv_bfloat16 g_A2[2][BB * 2048];     // [h1 | h2], parity-buffered
__device__ float         g_c[3 * BB * HH];
__device__ float         g_hvp[8 * BB * HH];     // hv split-K partials
__device__ __nv_bfloat16 g_w2bf[HH];
__device__ float         g_part[8 * BB * 4096]; // gate split-K partials
__device__ float         g_sc[BB * SS];
__device__ float         g_lm[BB * 8];           // lsm partial max
__device__ float         g_ls[BB * 8];           // lsm partial sum
__device__ unsigned      g_bcnt;   // grid barrier ticket counter (monotonic)
__device__ unsigned      g_bflag;  // grid barrier epoch flag (monotonic)

// ---------------- prologue (pack + cvt_x + zero + emb0 + w2) ----------------
__global__ void prolog_combined(
    const float* __restrict__ Wx, const float* __restrict__ Wh,
    const float* __restrict__ Wih0, const float* __restrict__ Whh0,
    const float* __restrict__ Wih1, const float* __restrict__ Whh1,
    const float* __restrict__ Wih2, const float* __restrict__ Whh2,
    const float* __restrict__ fcW, const float* __restrict__ x,
    const int* __restrict__ tseq, const float* __restrict__ emb,
    const float* __restrict__ w2) {
    const long long C0 = 98304, C1 = C0 + 131072, C2 = C1 + 1310720,
                    C3 = C2 + 1048576, C4 = C3 + 1048576, C5 = C4 + 4096000;
    long long idx = (long long)blockIdx.x * 256 + threadIdx.x;
    if (idx < C5) {
        uint4* dst; const float *s1, *s2 = nullptr;
        int N, K1, K2 = 0, tr; long long base;
        if (idx < C0)      { dst = g_pWx;  s1 = Wx;   N = HH;   K1 = EE;   tr = 1; base = 0; }
        else if (idx < C1) { dst = g_pWh;  s1 = Wh;   N = HH;   K1 = HH;   tr = 1; base = C0; }
        else if (idx < C2) { dst = g_pWc0; s1 = Wih0; s2 = Whh0; N = 4096; K1 = 1536; K2 = 1024; tr = 0; base = C1; }
        else if (idx < C3) { dst = g_pWc1; s1 = Wih1; s2 = Whh1; N = 4096; K1 = 1024; K2 = 1024; tr = 0; base = C2; }
        else if (idx < C4) { dst = g_pWc2; s1 = Wih2; s2 = Whh2; N = 4096; K1 = 1024; K2 = 1024; tr = 0; base = C3; }
        else               { dst = g_pFc;  s1 = fcW;  N = VV;   K1 = HH;   tr = 0; base = C4; }
        long long li = idx - base;
        int nch = (K1 + K2) >> 4;
        int lane = (int)(li & 31);
        long long tt = li >> 5;
        int ch = (int)(tt % nch);
        int nt = (int)(tt / nch);
        int g = lane >> 2, tig = lane & 3;
        int k = ch * 16 + tig * 2;
        int r0 = nt * 16 + g, r1 = r0 + 8;
        auto ld = [&](int n, int kk) -> float {
            if (kk < K1) return tr ? s1[(long long)kk * N + n] : s1[(long long)n * K1 + kk];
            return s2[(long long)n * HH + (kk - K1)];
        };
        auto p2 = [&](float a, float b) -> unsigned {
            __nv_bfloat162 h = __floats2bfloat162_rn(a, b);
            return *reinterpret_cast<unsigned*>(&h);
        };
        uint4 v;
        v.x = p2(ld(r0, k), ld(r0, k + 1));
        v.y = p2(ld(r0, k + 8), ld(r0, k + 9));
        v.z = p2(ld(r1, k), ld(r1, k + 1));
        v.w = p2(ld(r1, k + 8), ld(r1, k + 9));
        dst[li] = v;
        return;
    }
    long long r = idx - C5;
    if (r < (long long)BB * SS * EE) {
        g_xbf[r] = __float2bfloat16(x[r]);
        return;
    }
    r -= (long long)BB * SS * EE;
    if (r < 3 * BB * HH) {
        g_c[r] = 0.f;
        __nv_bfloat16 z = __float2bfloat16(0.f);
        if (r < BB * HH) {
            int b = (int)(r >> 10), j = (int)(r & 1023);
            g_A0[b * 2560 + 1536 + j] = z;
        }
        if (r < BB * 2048) { g_A1[r] = z; g_A2[0][r] = z; g_A2[1][r] = z; }
        return;
    }
    r -= 3 * BB * HH;
    if (r < BB * EE) {  // emb gather for t=0
        int b = (int)(r / EE), e = (int)(r % EE);
        int tok = tseq[b * TT];
        g_A0[b * 2560 + e] = __float2bfloat16(emb[(long long)tok * EE + e]);
        return;
    }
    r -= BB * EE;
    if (r < HH) g_w2bf[r] = __float2bfloat16(w2[r]);
}

// ---------------- mma + grid barrier helpers ----------------
__device__ __forceinline__ void mma16816(float c[4], uint32_t a0, uint32_t a1, uint32_t a2,
                                         uint32_t a3, uint32_t b0, uint32_t b1) {
    asm volatile(
        "mma.sync.aligned.m16n8k16.row.col.f32.bf16.bf16.f32 "
        "{%0,%1,%2,%3}, {%4,%5,%6,%7}, {%8,%9}, {%0,%1,%2,%3};\n"
        : "+f"(c[0]), "+f"(c[1]), "+f"(c[2]), "+f"(c[3])
        : "r"(a0), "r"(a1), "r"(a2), "r"(a3), "r"(b0), "r"(b1));
}

// epoch-based grid barrier for exactly 128 co-resident blocks; monotonic
__device__ __forceinline__ void gridbar() {
    __syncthreads();
    if (threadIdx.x == 0) {
        __threadfence();
        unsigned ticket = atomicAdd(&g_bcnt, 1u);
        unsigned epoch = ticket >> 7;
        if ((ticket & 127u) == 127u) {
            atomicExch(&g_bflag, epoch + 1u);
        } else {
            while (atomicAdd(&g_bflag, 0u) < epoch + 1u) __nanosleep(64);
        }
        __threadfence();
    }
    __syncthreads();
}

// ---------------- GEMM core (M=16, 256 n-cols/block, one K-slice) ----------
#define SAPITCH 328

__device__ __forceinline__ void gemm_core(
    char* smraw, const __nv_bfloat16* __restrict__ A, int lda,
    const uint4* __restrict__ B, int nchTot, int nCh, int nt, int z,
    float* __restrict__ C, int ldc) {
    __nv_bfloat16(*s_a)[SAPITCH] = reinterpret_cast<__nv_bfloat16(*)[SAPITCH]>(smraw);
    int w = threadIdx.x >> 5, lane = threadIdx.x & 31;
    int g = lane >> 2, tig = lane & 3;
    int n0 = nt * 256 + w * 32;
    int ch0 = z * nCh;
    int cols4 = nCh * 2;
    for (int idx = threadIdx.x; idx < 16 * cols4; idx += 256) {
        int r = idx / cols4, cc = idx % cols4;
        uint4 v = *reinterpret_cast<const uint4*>(A + (long long)r * lda + ch0 * 16 + cc * 8);
        *reinterpret_cast<uint4*>(&s_a[r][cc * 8]) = v;
    }
    __syncthreads();
    const uint4* bp0 = B + ((long long)(n0 >> 4) * nchTot + ch0) * 32 + lane;
    const uint4* bp1 = bp0 + (long long)nchTot * 32;
    uint32_t sab = (uint32_t)__cvta_generic_to_shared(&s_a[lane & 15][(lane >> 4) * 8]);
    float acc[4][4] = {{0.f}, {0.f}, {0.f}, {0.f}};
#pragma unroll 4
    for (int c = 0; c < nCh; c++) {
        uint4 b0 = __ldg(bp0 + (long long)c * 32);
        uint4 b1 = __ldg(bp1 + (long long)c * 32);
        uint32_t a0, a1, a2, a3;
        asm volatile("ldmatrix.sync.aligned.m8n8.x4.shared.b16 {%0,%1,%2,%3}, [%4];"
                     : "=r"(a0), "=r"(a1), "=r"(a2), "=r"(a3)
                     : "r"(sab + (uint32_t)c * 32));
        mma16816(acc[0], a0, a1, a2, a3, b0.x, b0.y);
        mma16816(acc[1], a0, a1, a2, a3, b0.z, b0.w);
        mma16816(acc[2], a0, a1, a2, a3, b1.x, b1.y);
        mma16816(acc[3], a0, a1, a2, a3, b1.z, b1.w);
    }
    int r0 = g, r1 = g + 8;
#pragma unroll
    for (int q = 0; q < 4; q++) {
        int col = n0 + q * 8 + tig * 2;
        C[(long long)r0 * ldc + col]     = acc[q][0];
        C[(long long)r0 * ldc + col + 1] = acc[q][1];
        C[(long long)r1 * ldc + col]     = acc[q][2];
        C[(long long)r1 * ldc + col + 1] = acc[q][3];
    }
}

// ---------------- LSTM cell phase (128 elements per block) ----------------
__device__ __forceinline__ void cell_phase(
    int layer, int blk, int t, int par,
    const float* __restrict__ bih, const float* __restrict__ bhh,
    const int* __restrict__ tseq, const float* __restrict__ emb) {
    int tid = threadIdx.x;
    if (tid < 128) {
        int idx = blk * 128 + tid;
        int b = idx >> 10, j = idx & 1023;
        float gi = bih[j] + bhh[j];
        float gf = bih[1024 + j] + bhh[1024 + j];
        float gg = bih[2048 + j] + bhh[2048 + j];
        float go = bih[3072 + j] + bhh[3072 + j];
#pragma unroll
        for (int p = 0; p < 8; p++) {
            const float* pp = g_part + p * (BB * 4096) + b * 4096;
            gi += __ldcg(pp + j);
            gf += __ldcg(pp + 1024 + j);
            gg += __ldcg(pp + 2048 + j);
            go += __ldcg(pp + 3072 + j);
        }
        float si = 1.f / (1.f + expf(-gi));
        float sf = 1.f / (1.f + expf(-gf));
        float so = 1.f / (1.f + expf(-go));
        float* cc = g_c + layer * (BB * HH) + idx;
        float cn = sf * (*cc) + si * tanhf(gg);
        *cc = cn;
        __nv_bfloat16 hb = __float2bfloat16(so * tanhf(cn));
        if (layer == 0) {
            g_A1[b * 2048 + j] = hb;
            g_A0[b * 2560 + 1536 + j] = hb;
        } else if (layer == 1) {
            g_A2[par][b * 2048 + j] = hb;
            g_A1[b * 2048 + 1024 + j] = hb;
        } else {
            g_A2[par ^ 1][b * 2048 + 1024 + j] = hb;
        }
    }
    if (layer == 2 && t + 1 < TT && tid < 96) {  // emb gather for step t+1
        int i2 = blk * 96 + tid;
        int be = i2 / EE, e = i2 % EE;
        int tok = tseq[be * TT + t + 1];
        g_A0[be * 2560 + e] = __float2bfloat16(emb[(long long)tok * EE + e]);
    }
}

// ---------------- the whole recurrent step: ONE kernel, 8 grid barriers --------
__global__ __launch_bounds__(256) void step_kernel(
    int t, const float* __restrict__ b2,
    const float* __restrict__ bih0, const float* __restrict__ bhh0,
    const float* __restrict__ bih1, const float* __restrict__ bhh1,
    const float* __restrict__ bih2, const float* __restrict__ bhh2,
    const int* __restrict__ tseq, const float* __restrict__ emb) {
    __shared__ __align__(16) char smraw[16 * SAPITCH * 2];
    int blk = blockIdx.x, tid = threadIdx.x;
    int par = t & 1;

    // ---- P0: hv = h2(t-1) @ Wh ----
    if (blk < 32)
        gemm_core(smraw, g_A2[par] + 1024, 2048, g_pWh, HH / 16, 8,
                  blk >> 3, blk & 7, g_hvp + (blk & 7) * (BB * HH), HH);
    gridbar();

    // ---- P1: scores ----
    {
        float* s_hv = reinterpret_cast<float*>(smraw);
        int b = blk >> 3, sch = blk & 7;
#pragma unroll
        for (int k = 0; k < 4; k++) {
            int i = k * 256 + tid;
            float s = 0.f;
#pragma unroll
            for (int p = 0; p < 8; p++) s += g_hvp[p * (BB * HH) + b * HH + i];
            s_hv[i] = s;
        }
        __syncthreads();
        int w = tid >> 5, lane = tid & 31;
        float bb2 = b2[0];
#pragma unroll
        for (int rr = 0; rr < 2; rr++) {
            int s = sch * 16 + w * 2 + rr;
            const __nv_bfloat16* row = g_xprojbf + ((long long)b * SS + s) * HH;
            float sum = 0.f;
#pragma unroll
            for (int it = 0; it < 4; it++) {
                int k0 = it * 256 + lane * 8;
                uint4 xv = *reinterpret_cast<const uint4*>(row + k0);
                uint4 wv = *reinterpret_cast<const uint4*>(g_w2bf + k0);
                const __nv_bfloat162* xp = reinterpret_cast<const __nv_bfloat162*>(&xv);
                const __nv_bfloat162* wp = reinterpret_cast<const __nv_bfloat162*>(&wv);
#pragma unroll
                for (int j = 0; j < 4; j++) {
                    float2 xf = __bfloat1622float2(xp[j]);
                    float2 wf = __bfloat1622float2(wp[j]);
                    float a = xf.x + s_hv[k0 + j * 2];
                    float c = xf.y + s_hv[k0 + j * 2 + 1];
                    sum += (a > 0.f ? a * wf.x : 0.f) + (c > 0.f ? c * wf.y : 0.f);
                }
            }
#pragma unroll
            for (int o = 16; o; o >>= 1) sum += __shfl_xor_sync(0xffffffffu, sum, o);
            if (!lane) g_sc[b * SS + s] = sum + bb2;
        }
    }
    gridbar();

    // ---- P2: log-softmax + context ----
    {
        float* sc = reinterpret_cast<float*>(smraw);
        float* red = sc + 128;
        float* part = sc + 132;
        int b = blk >> 3, ech = blk & 7;
        if (tid < SS) sc[tid] = g_sc[b * SS + tid];
        __syncthreads();
        if (tid < 32) {
            float m = -1e30f;
#pragma unroll
            for (int i = 0; i < 4; i++) m = fmaxf(m, sc[tid + i * 32]);
#pragma unroll
            for (int o = 16; o; o >>= 1) m = fmaxf(m, __shfl_xor_sync(0xffffffffu, m, o));
            float su = 0.f;
#pragma unroll
            for (int i = 0; i < 4; i++) su += expf(sc[tid + i * 32] - m);
#pragma unroll
            for (int o = 16; o; o >>= 1) su += __shfl_xor_sync(0xffffffffu, su, o);
            if (!tid) *red = m + logf(su);
        }
        __syncthreads();
        float lse = *red;
        __syncthreads();
        if (tid < SS) sc[tid] -= lse;
        __syncthreads();
        if (tid < 192) {
            int q = tid / 96, e = tid % 96;
            int eg = ech * 96 + e;
            const __nv_bfloat16* xb = g_xbf + ((long long)b * SS + q * 64) * EE + eg;
            float acc = 0.f;
#pragma unroll 8
            for (int ss = 0; ss < 64; ss++)
                acc += sc[q * 64 + ss] * __bfloat162float(xb[(long long)ss * EE]);
            part[q * 96 + e] = acc;
        }
        __syncthreads();
        if (tid < 96) {
            float a = part[tid] + part[96 + tid];
            g_A0[b * 2560 + EE + ech * 96 + tid] = __float2bfloat16(a);
        }
    }
    gridbar();

    // ---- P3/P4: layer 0 ----
    gemm_core(smraw, g_A0, 2560, g_pWc0, 2560 / 16, 20, blk >> 3, blk & 7,
              g_part + (blk & 7) * (BB * 4096), 4096);
    gridbar();
    cell_phase(0, blk, t, par, bih0, bhh0, tseq, emb);
    gridbar();

    // ---- P5/P6: layer 1 ----
    gemm_core(smraw, g_A1, 2048, g_pWc1, 2048 / 16, 16, blk >> 3, blk & 7,
              g_part + (blk & 7) * (BB * 4096), 4096);
    gridbar();
    cell_phase(1, blk, t, par, bih1, bhh1, tseq, emb);
    gridbar();

    // ---- P7/P8: layer 2 ----
    gemm_core(smraw, g_A2[par], 2048, g_pWc2, 2048 / 16, 16, blk >> 3, blk & 7,
              g_part + (blk & 7) * (BB * 4096), 4096);
    gridbar();
    cell_phase(2, blk, t, par, bih2, bhh2, tseq, emb);
}

// ---------------- standalone GEMM for x_proj (256 thr, 256 cols/block) --------
#define APAD 8
#define AMAXC (64 * 16)

__global__ __launch_bounds__(256) void gemm_xproj(
    const float* __restrict__ bias) {
    __shared__ __nv_bfloat16 s_a[16][AMAXC + APAD];
    const __nv_bfloat16* A = g_xbf;
    const uint4* B = g_pWx;
    int nchTot = EE / 16, nCh = 48;
    int w = threadIdx.x >> 5, lane = threadIdx.x & 31;
    int g = lane >> 2, tig = lane & 3;
    int m0 = blockIdx.y * 16;
    int n0 = blockIdx.x * 256 + w * 32;
    {
        int cols4 = nCh * 2;
        for (int idx = threadIdx.x; idx < 16 * cols4; idx += 256) {
            int r = idx / cols4, cc = idx % cols4;
            uint4 v = *reinterpret_cast<const uint4*>(
                A + (long long)(m0 + r) * EE + cc * 8);
            *reinterpret_cast<uint4*>(&s_a[r][cc * 8]) = v;
        }
    }
    __syncthreads();
    const uint4* bp0 = B + ((long long)(n0 >> 4) * nchTot) * 32 + lane;
    const uint4* bp1 = bp0 + (long long)nchTot * 32;
    uint32_t sab = (uint32_t)__cvta_generic_to_shared(&s_a[lane & 15][(lane >> 4) * 8]);
    float acc[4][4] = {{0.f}, {0.f}, {0.f}, {0.f}};
#pragma unroll 8
    for (int c = 0; c < nCh; c++) {
        uint4 b0 = __ldg(bp0 + (long long)c * 32);
        uint4 b1 = __ldg(bp1 + (long long)c * 32);
        uint32_t a0, a1, a2, a3;
        asm volatile("ldmatrix.sync.aligned.m8n8.x4.shared.b16 {%0,%1,%2,%3}, [%4];"
                     : "=r"(a0), "=r"(a1), "=r"(a2), "=r"(a3)
                     : "r"(sab + (uint32_t)c * 32));
        mma16816(acc[0], a0, a1, a2, a3, b0.x, b0.y);
        mma16816(acc[1], a0, a1, a2, a3, b0.z, b0.w);
        mma16816(acc[2], a0, a1, a2, a3, b1.x, b1.y);
        mma16816(acc[3], a0, a1, a2, a3, b1.z, b1.w);
    }
    int r0 = m0 + g, r1 = m0 + g + 8;
#pragma unroll
    for (int q = 0; q < 4; q++) {
        int col = n0 + q * 8 + tig * 2;
        float bv0 = bias[col], bv1 = bias[col + 1];
        g_xprojbf[(long long)r0 * HH + col]     = __float2bfloat16(acc[q][0] + bv0);
        g_xprojbf[(long long)r0 * HH + col + 1] = __float2bfloat16(acc[q][1] + bv1);
        g_xprojbf[(long long)r1 * HH + col]     = __float2bfloat16(acc[q][2] + bv0);
        g_xprojbf[(long long)r1 * HH + col + 1] = __float2bfloat16(acc[q][3] + bv1);
    }
}

// ---------------- fc GEMM: 250 blocks x 256 thr, 8 warps x 16 cols ----------
__global__ __launch_bounds__(256) void fc_gemm(
    int par1, float* __restrict__ C, const float* __restrict__ bias) {
    __shared__ __nv_bfloat16 s_a[16][AMAXC + APAD];
    const __nv_bfloat16* A = g_A2[par1] + 1024;  // h2, lda 2048
    const int nchTot = HH / 16, nCh = 64;
    int w = threadIdx.x >> 5, lane = threadIdx.x & 31;
    int g = lane >> 2, tig = lane & 3;
    int n0 = blockIdx.x * 128 + w * 16;
    {
        int cols4 = nCh * 2;  // 128 uint4 per row
        for (int idx = threadIdx.x; idx < 16 * cols4; idx += 256) {
            int r = idx / cols4, cc = idx % cols4;
            uint4 v = *reinterpret_cast<const uint4*>(A + (long long)r * 2048 + cc * 8);
            *reinterpret_cast<uint4*>(&s_a[r][cc * 8]) = v;
        }
    }
    __syncthreads();
    const uint4* bp = g_pFc + ((long long)(n0 >> 4) * nchTot) * 32 + lane;
    uint32_t sab = (uint32_t)__cvta_generic_to_shared(&s_a[lane & 15][(lane >> 4) * 8]);
    float acc[2][4] = {{0.f}, {0.f}};
#pragma unroll 8
    for (int c = 0; c < nCh; c++) {
        uint4 b0 = __ldcs(bp + (long long)c * 32);
        uint32_t a0, a1, a2, a3;
        asm volatile("ldmatrix.sync.aligned.m8n8.x4.shared.b16 {%0,%1,%2,%3}, [%4];"
                     : "=r"(a0), "=r"(a1), "=r"(a2), "=r"(a3)
                     : "r"(sab + (uint32_t)c * 32));
        mma16816(acc[0], a0, a1, a2, a3, b0.x, b0.y);
        mma16816(acc[1], a0, a1, a2, a3, b0.z, b0.w);
    }
    int r0 = g, r1 = g + 8;
#pragma unroll
    for (int q = 0; q < 2; q++) {
        int col = n0 + q * 8 + tig * 2;
        float bv0 = bias[col], bv1 = bias[col + 1];
        C[(long long)r0 * (TT * VV) + col]     = acc[q][0] + bv0;
        C[(long long)r0 * (TT * VV) + col + 1] = acc[q][1] + bv1;
        C[(long long)r1 * (TT * VV) + col]     = acc[q][2] + bv0;
        C[(long long)r1 * (TT * VV) + col + 1] = acc[q][3] + bv1;
    }
}

// ---------------- lsm stage 1: per-chunk max + exp-sum (8 x 16 blocks) --------
__global__ __launch_bounds__(256) void lsm_part(const float* __restrict__ dout, int t) {
    int b = blockIdx.y, c = blockIdx.x;  // 8 chunks of 4000
    const float4* row = reinterpret_cast<const float4*>(
        dout + (long long)b * TT * VV + (long long)t * VV) + c * 1000;
    __shared__ float sm[8];
    int tid = threadIdx.x, lane = tid & 31, wid = tid >> 5;
    float m = -1e30f;
    for (int i = tid; i < 1000; i += 256) {
        float4 v = row[i];
        m = fmaxf(m, fmaxf(fmaxf(v.x, v.y), fmaxf(v.z, v.w)));
    }
#pragma unroll
    for (int o = 16; o; o >>= 1) m = fmaxf(m, __shfl_xor_sync(0xffffffffu, m, o));
    if (!lane) sm[wid] = m;
    __syncthreads();
    float M = fmaxf(fmaxf(fmaxf(sm[0], sm[1]), fmaxf(sm[2], sm[3])),
                    fmaxf(fmaxf(sm[4], sm[5]), fmaxf(sm[6], sm[7])));
    float s = 0.f;
    for (int i = tid; i < 1000; i += 256) {
        float4 v = row[i];
        s += expf(v.x - M) + expf(v.y - M) + expf(v.z - M) + expf(v.w - M);
    }
#pragma unroll
    for (int o = 16; o; o >>= 1) s += __shfl_xor_sync(0xffffffffu, s, o);
    __syncthreads();
    if (!lane) sm[wid] = s;
    __syncthreads();
    if (!tid) {
        float S = 0.f;
#pragma unroll
        for (int i = 0; i < 8; i++) S += sm[i];
        g_lm[b * 8 + c] = M;
        g_ls[b * 8 + c] = S;
    }
}

// ---------------- lsm stage 2: combine + subtract (16 x 16 blocks) ------------
__global__ __launch_bounds__(256) void lsm_fin(float* __restrict__ dout, int t) {
    int b = blockIdx.y, c2 = blockIdx.x;  // 16 chunks of 2000
    __shared__ float lse_s;
    if (!threadIdx.x) {
        float M = -1e30f;
#pragma unroll
        for (int k = 0; k < 8; k++) M = fmaxf(M, g_lm[b * 8 + k]);
        float S = 0.f;
#pragma unroll
        for (int k = 0; k < 8; k++) S += g_ls[b * 8 + k] * expf(g_lm[b * 8 + k] - M);
        lse_s = M + logf(S);
    }
    __syncthreads();
    float lse = lse_s;
    float4* row = reinterpret_cast<float4*>(
        dout + (long long)b * TT * VV + (long long)t * VV) + c2 * 500;
    for (int i = threadIdx.x; i < 500; i += 256) {
        float4 v = row[i];
        v.x -= lse; v.y -= lse; v.z -= lse; v.w -= lse;
        row[i] = v;
    }
}

// ---------------- host launch ----------------
extern "C" void kernel_launch(void* const* d_in, const int* in_sizes, int n_in,
                              void* d_out, int out_size) {
    const float* x    = (const float*)d_in[0];
    const int*   tseq = (const int*)d_in[1];
    const float* emb  = (const float*)d_in[2];
    const float* Wx   = (const float*)d_in[3];
    const float* Wh   = (const float*)d_in[4];
    const float* b1   = (const float*)d_in[5];
    const float* w2   = (const float*)d_in[6];
    const float* b2   = (const float*)d_in[7];
    const float* fcW  = (const float*)d_in[8];
    const float* fcb  = (const float*)d_in[9];
    const float* Wih0 = (const float*)d_in[10];
    const float* Whh0 = (const float*)d_in[11];
    const float* bih0 = (const float*)d_in[12];
    const float* bhh0 = (const float*)d_in[13];
    const float* Wih1 = (const float*)d_in[14];
    const float* Whh1 = (const float*)d_in[15];
    const float* bih1 = (const float*)d_in[16];
    const float* bhh1 = (const float*)d_in[17];
    const float* Wih2 = (const float*)d_in[18];
    const float* Whh2 = (const float*)d_in[19];
    const float* bih2 = (const float*)d_in[20];
    const float* bhh2 = (const float*)d_in[21];
    float* dout = (float*)d_out;

    static cudaStream_t s2 = nullptr;
    static cudaEvent_t evA = nullptr, evB0 = nullptr, evB1 = nullptr, evEnd = nullptr;
    if (!s2) {
        cudaStreamCreateWithFlags(&s2, cudaStreamNonBlocking);
        cudaEventCreateWithFlags(&evA, cudaEventDisableTiming);
        cudaEventCreateWithFlags(&evB0, cudaEventDisableTiming);
        cudaEventCreateWithFlags(&evB1, cudaEventDisableTiming);
        cudaEventCreateWithFlags(&evEnd, cudaEventDisableTiming);
    }

    // -------- prologue --------
    prolog_combined<<<36596, 256>>>(Wx, Wh, Wih0, Whh0, Wih1, Whh1, Wih2, Whh2, fcW,
                                    x, tseq, emb, w2);
    gemm_xproj<<<dim3(4, 128), 256>>>(b1);

    // -------- time loop: 1 chain kernel per step + fc/lsm on side stream ------
    for (int t = 0; t < TT; t++) {
        if (t >= 2) cudaStreamWaitEvent(0, (t & 1) ? evB1 : evB0, 0);
        step_kernel<<<128, 256>>>(t, b2, bih0, bhh0, bih1, bhh1, bih2, bhh2, tseq, emb);
        cudaEventRecord(evA, 0);
        cudaStreamWaitEvent(s2, evA, 0);
        // fc: 250 blocks x 256 threads, 8 warps x 16 cols = 128 cols/block
        fc_gemm<<<250, 256, 0, s2>>>((t + 1) & 1, dout + (long long)t * VV, fcb);
        cudaEventRecord((t & 1) ? evB1 : evB0, s2);
        lsm_part<<<dim3(8, BB), 256, 0, s2>>>(dout, t);
        lsm_fin<<<dim3(16, BB), 256, 0, s2>>>(dout, t);
    }
    cudaEventRecord(evEnd, s2);
    cudaStreamWaitEvent(0, evEnd, 0);
}

// round 17
// speedup vs baseline: 1.1370x; 1.1370x over previous
#include <cuda_runtime.h>
#include <cuda_bf16.h>
#include <cstdint>

#define BB 16
#define SS 128
#define TT 64
#define EE 768
#define HH 1024
#define VV 32000

// ---------------- device scratch (static, no allocation) ----------------
__device__ __nv_bfloat16 g_xbf[BB * SS * EE];
__device__ __nv_bfloat16 g_xprojbf[BB * SS * HH];
__device__ uint4 g_pWx[(HH / 16) * (EE / 16) * 32];
__device__ uint4 g_pWh[(HH / 16) * (HH / 16) * 32];
__device__ uint4 g_pWc0[(4096 / 16) * (2560 / 16) * 32];
__device__ uint4 g_pWc1[(4096 / 16) * (2048 / 16) * 32];
__device__ uint4 g_pWc2[(4096 / 16) * (2048 / 16) * 32];
__device__ uint4 g_pFc[(VV / 16) * (HH / 16) * 32];

__device__ __nv_bfloat16 g_A0[BB * 2560];        // [emb | ctx | h0]
__device__ __nv_bfloat16 g_A1[BB * 2048];        // [h0 | h1_prev]
__device__ __nv_bfloat16 g_A2[2][BB * 2048];     // [h1 | h2], parity-buffered
__device__ float         g_c[3 * BB * HH];
__device__ float         g_hvp[8 * BB * HH];     // hv split-K partials
__device__ __nv_bfloat16 g_w2bf[HH];
__device__ float         g_part[8 * BB * 4096]; // gate split-K partials
__device__ float         g_sc[BB * SS];
__device__ unsigned      g_bcnt;   // grid barrier ticket counter (monotonic)
__device__ unsigned      g_bflag;  // grid barrier epoch flag (monotonic)

// ---------------- prologue (pack + cvt_x + zero + emb0 + w2) ----------------
__global__ void prolog_combined(
    const float* __restrict__ Wx, const float* __restrict__ Wh,
    const float* __restrict__ Wih0, const float* __restrict__ Whh0,
    const float* __restrict__ Wih1, const float* __restrict__ Whh1,
    const float* __restrict__ Wih2, const float* __restrict__ Whh2,
    const float* __restrict__ fcW, const float* __restrict__ x,
    const int* __restrict__ tseq, const float* __restrict__ emb,
    const float* __restrict__ w2) {
    const long long C0 = 98304, C1 = C0 + 131072, C2 = C1 + 1310720,
                    C3 = C2 + 1048576, C4 = C3 + 1048576, C5 = C4 + 4096000;
    long long idx = (long long)blockIdx.x * 256 + threadIdx.x;
    if (idx < C5) {
        uint4* dst; const float *s1, *s2 = nullptr;
        int N, K1, K2 = 0, tr; long long base;
        if (idx < C0)      { dst = g_pWx;  s1 = Wx;   N = HH;   K1 = EE;   tr = 1; base = 0; }
        else if (idx < C1) { dst = g_pWh;  s1 = Wh;   N = HH;   K1 = HH;   tr = 1; base = C0; }
        else if (idx < C2) { dst = g_pWc0; s1 = Wih0; s2 = Whh0; N = 4096; K1 = 1536; K2 = 1024; tr = 0; base = C1; }
        else if (idx < C3) { dst = g_pWc1; s1 = Wih1; s2 = Whh1; N = 4096; K1 = 1024; K2 = 1024; tr = 0; base = C2; }
        else if (idx < C4) { dst = g_pWc2; s1 = Wih2; s2 = Whh2; N = 4096; K1 = 1024; K2 = 1024; tr = 0; base = C3; }
        else               { dst = g_pFc;  s1 = fcW;  N = VV;   K1 = HH;   tr = 0; base = C4; }
        long long li = idx - base;
        int nch = (K1 + K2) >> 4;
        int lane = (int)(li & 31);
        long long tt = li >> 5;
        int ch = (int)(tt % nch);
        int nt = (int)(tt / nch);
        int g = lane >> 2, tig = lane & 3;
        int k = ch * 16 + tig * 2;
        int r0 = nt * 16 + g, r1 = r0 + 8;
        auto ld = [&](int n, int kk) -> float {
            if (kk < K1) return tr ? s1[(long long)kk * N + n] : s1[(long long)n * K1 + kk];
            return s2[(long long)n * HH + (kk - K1)];
        };
        auto p2 = [&](float a, float b) -> unsigned {
            __nv_bfloat162 h = __floats2bfloat162_rn(a, b);
            return *reinterpret_cast<unsigned*>(&h);
        };
        uint4 v;
        v.x = p2(ld(r0, k), ld(r0, k + 1));
        v.y = p2(ld(r0, k + 8), ld(r0, k + 9));
        v.z = p2(ld(r1, k), ld(r1, k + 1));
        v.w = p2(ld(r1, k + 8), ld(r1, k + 9));
        dst[li] = v;
        return;
    }
    long long r = idx - C5;
    if (r < (long long)BB * SS * EE) {
        g_xbf[r] = __float2bfloat16(x[r]);
        return;
    }
    r -= (long long)BB * SS * EE;
    if (r < 3 * BB * HH) {
        g_c[r] = 0.f;
        __nv_bfloat16 z = __float2bfloat16(0.f);
        if (r < BB * HH) {
            int b = (int)(r >> 10), j = (int)(r & 1023);
            g_A0[b * 2560 + 1536 + j] = z;
        }
        if (r < BB * 2048) { g_A1[r] = z; g_A2[0][r] = z; g_A2[1][r] = z; }
        return;
    }
    r -= 3 * BB * HH;
    if (r < BB * EE) {  // emb gather for t=0
        int b = (int)(r / EE), e = (int)(r % EE);
        int tok = tseq[b * TT];
        g_A0[b * 2560 + e] = __float2bfloat16(emb[(long long)tok * EE + e]);
        return;
    }
    r -= BB * EE;
    if (r < HH) g_w2bf[r] = __float2bfloat16(w2[r]);
}

// ---------------- mma + grid barrier helpers ----------------
__device__ __forceinline__ void mma16816(float c[4], uint32_t a0, uint32_t a1, uint32_t a2,
                                         uint32_t a3, uint32_t b0, uint32_t b1) {
    asm volatile(
        "mma.sync.aligned.m16n8k16.row.col.f32.bf16.bf16.f32 "
        "{%0,%1,%2,%3}, {%4,%5,%6,%7}, {%8,%9}, {%0,%1,%2,%3};\n"
        : "+f"(c[0]), "+f"(c[1]), "+f"(c[2]), "+f"(c[3])
        : "r"(a0), "r"(a1), "r"(a2), "r"(a3), "r"(b0), "r"(b1));
}

// epoch-based grid barrier for exactly 128 co-resident blocks; monotonic
__device__ __forceinline__ void gridbar() {
    __syncthreads();
    if (threadIdx.x == 0) {
        __threadfence();
        unsigned ticket = atomicAdd(&g_bcnt, 1u);
        unsigned epoch = ticket >> 7;
        if ((ticket & 127u) == 127u) {
            atomicExch(&g_bflag, epoch + 1u);
        } else {
            while (atomicAdd(&g_bflag, 0u) < epoch + 1u) __nanosleep(64);
        }
        __threadfence();
    }
    __syncthreads();
}

// ---------------- GEMM core (M=16, 256 n-cols/block, one K-slice) ----------
#define SAPITCH 328

__device__ __forceinline__ void gemm_core(
    char* smraw, const __nv_bfloat16* __restrict__ A, int lda,
    const uint4* __restrict__ B, int nchTot, int nCh, int nt, int z,
    float* __restrict__ C, int ldc) {
    __nv_bfloat16(*s_a)[SAPITCH] = reinterpret_cast<__nv_bfloat16(*)[SAPITCH]>(smraw);
    int w = threadIdx.x >> 5, lane = threadIdx.x & 31;
    int g = lane >> 2, tig = lane & 3;
    int n0 = nt * 256 + w * 32;
    int ch0 = z * nCh;
    int cols4 = nCh * 2;
    for (int idx = threadIdx.x; idx < 16 * cols4; idx += 256) {
        int r = idx / cols4, cc = idx % cols4;
        uint4 v = *reinterpret_cast<const uint4*>(A + (long long)r * lda + ch0 * 16 + cc * 8);
        *reinterpret_cast<uint4*>(&s_a[r][cc * 8]) = v;
    }
    __syncthreads();
    const uint4* bp0 = B + ((long long)(n0 >> 4) * nchTot + ch0) * 32 + lane;
    const uint4* bp1 = bp0 + (long long)nchTot * 32;
    uint32_t sab = (uint32_t)__cvta_generic_to_shared(&s_a[lane & 15][(lane >> 4) * 8]);
    float acc[4][4] = {{0.f}, {0.f}, {0.f}, {0.f}};
#pragma unroll 4
    for (int c = 0; c < nCh; c++) {
        uint4 b0 = __ldg(bp0 + (long long)c * 32);
        uint4 b1 = __ldg(bp1 + (long long)c * 32);
        uint32_t a0, a1, a2, a3;
        asm volatile("ldmatrix.sync.aligned.m8n8.x4.shared.b16 {%0,%1,%2,%3}, [%4];"
                     : "=r"(a0), "=r"(a1), "=r"(a2), "=r"(a3)
                     : "r"(sab + (uint32_t)c * 32));
        mma16816(acc[0], a0, a1, a2, a3, b0.x, b0.y);
        mma16816(acc[1], a0, a1, a2, a3, b0.z, b0.w);
        mma16816(acc[2], a0, a1, a2, a3, b1.x, b1.y);
        mma16816(acc[3], a0, a1, a2, a3, b1.z, b1.w);
    }
    int r0 = g, r1 = g + 8;
#pragma unroll
    for (int q = 0; q < 4; q++) {
        int col = n0 + q * 8 + tig * 2;
        C[(long long)r0 * ldc + col]     = acc[q][0];
        C[(long long)r0 * ldc + col + 1] = acc[q][1];
        C[(long long)r1 * ldc + col]     = acc[q][2];
        C[(long long)r1 * ldc + col + 1] = acc[q][3];
    }
}

// ---------------- LSTM cell phase (128 elements per block) ----------------
__device__ __forceinline__ void cell_phase(
    int layer, int blk, int t, int par,
    const float* __restrict__ bih, const float* __restrict__ bhh,
    const int* __restrict__ tseq, const float* __restrict__ emb) {
    int tid = threadIdx.x;
    if (tid < 128) {
        int idx = blk * 128 + tid;
        int b = idx >> 10, j = idx & 1023;
        float gi = bih[j] + bhh[j];
        float gf = bih[1024 + j] + bhh[1024 + j];
        float gg = bih[2048 + j] + bhh[2048 + j];
        float go = bih[3072 + j] + bhh[3072 + j];
#pragma unroll
        for (int p = 0; p < 8; p++) {
            const float* pp = g_part + p * (BB * 4096) + b * 4096;
            gi += __ldcg(pp + j);
            gf += __ldcg(pp + 1024 + j);
            gg += __ldcg(pp + 2048 + j);
            go += __ldcg(pp + 3072 + j);
        }
        float si = 1.f / (1.f + expf(-gi));
        float sf = 1.f / (1.f + expf(-gf));
        float so = 1.f / (1.f + expf(-go));
        float* cc = g_c + layer * (BB * HH) + idx;
        float cn = sf * (*cc) + si * tanhf(gg);
        *cc = cn;
        __nv_bfloat16 hb = __float2bfloat16(so * tanhf(cn));
        if (layer == 0) {
            g_A1[b * 2048 + j] = hb;
            g_A0[b * 2560 + 1536 + j] = hb;
        } else if (layer == 1) {
            g_A2[par][b * 2048 + j] = hb;
            g_A1[b * 2048 + 1024 + j] = hb;
        } else {
            g_A2[par ^ 1][b * 2048 + 1024 + j] = hb;
        }
    }
    if (layer == 2 && t + 1 < TT && tid < 96) {  // emb gather for step t+1
        int i2 = blk * 96 + tid;
        int be = i2 / EE, e = i2 % EE;
        int tok = tseq[be * TT + t + 1];
        g_A0[be * 2560 + e] = __float2bfloat16(emb[(long long)tok * EE + e]);
    }
}

// ---------------- the whole recurrent step: ONE kernel, 8 grid barriers --------
__global__ __launch_bounds__(256) void step_kernel(
    int t, const float* __restrict__ b2,
    const float* __restrict__ bih0, const float* __restrict__ bhh0,
    const float* __restrict__ bih1, const float* __restrict__ bhh1,
    const float* __restrict__ bih2, const float* __restrict__ bhh2,
    const int* __restrict__ tseq, const float* __restrict__ emb) {
    __shared__ __align__(16) char smraw[16 * SAPITCH * 2];
    int blk = blockIdx.x, tid = threadIdx.x;
    int par = t & 1;

    // ---- P0: hv = h2(t-1) @ Wh ----
    if (blk < 32)
        gemm_core(smraw, g_A2[par] + 1024, 2048, g_pWh, HH / 16, 8,
                  blk >> 3, blk & 7, g_hvp + (blk & 7) * (BB * HH), HH);
    gridbar();

    // ---- P1: scores ----
    {
        float* s_hv = reinterpret_cast<float*>(smraw);
        int b = blk >> 3, sch = blk & 7;
#pragma unroll
        for (int k = 0; k < 4; k++) {
            int i = k * 256 + tid;
            float s = 0.f;
#pragma unroll
            for (int p = 0; p < 8; p++) s += g_hvp[p * (BB * HH) + b * HH + i];
            s_hv[i] = s;
        }
        __syncthreads();
        int w = tid >> 5, lane = tid & 31;
        float bb2 = b2[0];
#pragma unroll
        for (int rr = 0; rr < 2; rr++) {
            int s = sch * 16 + w * 2 + rr;
            const __nv_bfloat16* row = g_xprojbf + ((long long)b * SS + s) * HH;
            float sum = 0.f;
#pragma unroll
            for (int it = 0; it < 4; it++) {
                int k0 = it * 256 + lane * 8;
                uint4 xv = *reinterpret_cast<const uint4*>(row + k0);
                uint4 wv = *reinterpret_cast<const uint4*>(g_w2bf + k0);
                const __nv_bfloat162* xp = reinterpret_cast<const __nv_bfloat162*>(&xv);
                const __nv_bfloat162* wp = reinterpret_cast<const __nv_bfloat162*>(&wv);
#pragma unroll
                for (int j = 0; j < 4; j++) {
                    float2 xf = __bfloat1622float2(xp[j]);
                    float2 wf = __bfloat1622float2(wp[j]);
                    float a = xf.x + s_hv[k0 + j * 2];
                    float c = xf.y + s_hv[k0 + j * 2 + 1];
                    sum += (a > 0.f ? a * wf.x : 0.f) + (c > 0.f ? c * wf.y : 0.f);
                }
            }
#pragma unroll
            for (int o = 16; o; o >>= 1) sum += __shfl_xor_sync(0xffffffffu, sum, o);
            if (!lane) g_sc[b * SS + s] = sum + bb2;
        }
    }
    gridbar();

    // ---- P2: log-softmax + context ----
    {
        float* sc = reinterpret_cast<float*>(smraw);
        float* red = sc + 128;
        float* part = sc + 132;
        int b = blk >> 3, ech = blk & 7;
        if (tid < SS) sc[tid] = g_sc[b * SS + tid];
        __syncthreads();
        if (tid < 32) {
            float m = -1e30f;
#pragma unroll
            for (int i = 0; i < 4; i++) m = fmaxf(m, sc[tid + i * 32]);
#pragma unroll
            for (int o = 16; o; o >>= 1) m = fmaxf(m, __shfl_xor_sync(0xffffffffu, m, o));
            float su = 0.f;
#pragma unroll
            for (int i = 0; i < 4; i++) su += expf(sc[tid + i * 32] - m);
#pragma unroll
            for (int o = 16; o; o >>= 1) su += __shfl_xor_sync(0xffffffffu, su, o);
            if (!tid) *red = m + logf(su);
        }
        __syncthreads();
        float lse = *red;
        __syncthreads();
        if (tid < SS) sc[tid] -= lse;
        __syncthreads();
        if (tid < 192) {
            int q = tid / 96, e = tid % 96;
            int eg = ech * 96 + e;
            const __nv_bfloat16* xb = g_xbf + ((long long)b * SS + q * 64) * EE + eg;
            float acc = 0.f;
#pragma unroll 8
            for (int ss = 0; ss < 64; ss++)
                acc += sc[q * 64 + ss] * __bfloat162float(xb[(long long)ss * EE]);
            part[q * 96 + e] = acc;
        }
        __syncthreads();
        if (tid < 96) {
            float a = part[tid] + part[96 + tid];
            g_A0[b * 2560 + EE + ech * 96 + tid] = __float2bfloat16(a);
        }
    }
    gridbar();

    // ---- P3/P4: layer 0 ----
    gemm_core(smraw, g_A0, 2560, g_pWc0, 2560 / 16, 20, blk >> 3, blk & 7,
              g_part + (blk & 7) * (BB * 4096), 4096);
    gridbar();
    cell_phase(0, blk, t, par, bih0, bhh0, tseq, emb);
    gridbar();

    // ---- P5/P6: layer 1 ----
    gemm_core(smraw, g_A1, 2048, g_pWc1, 2048 / 16, 16, blk >> 3, blk & 7,
              g_part + (blk & 7) * (BB * 4096), 4096);
    gridbar();
    cell_phase(1, blk, t, par, bih1, bhh1, tseq, emb);
    gridbar();

    // ---- P7/P8: layer 2 ----
    gemm_core(smraw, g_A2[par], 2048, g_pWc2, 2048 / 16, 16, blk >> 3, blk & 7,
              g_part + (blk & 7) * (BB * 4096), 4096);
    gridbar();
    cell_phase(2, blk, t, par, bih2, bhh2, tseq, emb);
}

// ---------------- standalone GEMM for x_proj (256 thr, 256 cols/block) --------
#define APAD 8
#define AMAXC (64 * 16)

__global__ __launch_bounds__(256) void gemm_xproj(const float* __restrict__ bias) {
    __shared__ __nv_bfloat16 s_a[16][AMAXC + APAD];
    const __nv_bfloat16* A = g_xbf;
    const uint4* B = g_pWx;
    int nchTot = EE / 16, nCh = 48;
    int w = threadIdx.x >> 5, lane = threadIdx.x & 31;
    int g = lane >> 2, tig = lane & 3;
    int m0 = blockIdx.y * 16;
    int n0 = blockIdx.x * 256 + w * 32;
    {
        int cols4 = nCh * 2;
        for (int idx = threadIdx.x; idx < 16 * cols4; idx += 256) {
            int r = idx / cols4, cc = idx % cols4;
            uint4 v = *reinterpret_cast<const uint4*>(
                A + (long long)(m0 + r) * EE + cc * 8);
            *reinterpret_cast<uint4*>(&s_a[r][cc * 8]) = v;
        }
    }
    __syncthreads();
    const uint4* bp0 = B + ((long long)(n0 >> 4) * nchTot) * 32 + lane;
    const uint4* bp1 = bp0 + (long long)nchTot * 32;
    uint32_t sab = (uint32_t)__cvta_generic_to_shared(&s_a[lane & 15][(lane >> 4) * 8]);
    float acc[4][4] = {{0.f}, {0.f}, {0.f}, {0.f}};
#pragma unroll 8
    for (int c = 0; c < nCh; c++) {
        uint4 b0 = __ldg(bp0 + (long long)c * 32);
        uint4 b1 = __ldg(bp1 + (long long)c * 32);
        uint32_t a0, a1, a2, a3;
        asm volatile("ldmatrix.sync.aligned.m8n8.x4.shared.b16 {%0,%1,%2,%3}, [%4];"
                     : "=r"(a0), "=r"(a1), "=r"(a2), "=r"(a3)
                     : "r"(sab + (uint32_t)c * 32));
        mma16816(acc[0], a0, a1, a2, a3, b0.x, b0.y);
        mma16816(acc[1], a0, a1, a2, a3, b0.z, b0.w);
        mma16816(acc[2], a0, a1, a2, a3, b1.x, b1.y);
        mma16816(acc[3], a0, a1, a2, a3, b1.z, b1.w);
    }
    int r0 = m0 + g, r1 = m0 + g + 8;
#pragma unroll
    for (int q = 0; q < 4; q++) {
        int col = n0 + q * 8 + tig * 2;
        float bv0 = bias[col], bv1 = bias[col + 1];
        g_xprojbf[(long long)r0 * HH + col]     = __float2bfloat16(acc[q][0] + bv0);
        g_xprojbf[(long long)r0 * HH + col + 1] = __float2bfloat16(acc[q][1] + bv1);
        g_xprojbf[(long long)r1 * HH + col]     = __float2bfloat16(acc[q][2] + bv0);
        g_xprojbf[(long long)r1 * HH + col + 1] = __float2bfloat16(acc[q][3] + bv1);
    }
}

// ---------------- fc GEMM (R14 config: 125 blocks x 256 thr, 32 cols/warp) ----
__global__ __launch_bounds__(256) void fc_gemm(
    int par1, float* __restrict__ C, const float* __restrict__ bias) {
    __shared__ __nv_bfloat16 s_a[16][AMAXC + APAD];
    const __nv_bfloat16* A = g_A2[par1] + 1024;  // h2, lda 2048
    const int nchTot = HH / 16, nCh = 64;
    int w = threadIdx.x >> 5, lane = threadIdx.x & 31;
    int g = lane >> 2, tig = lane & 3;
    int n0 = blockIdx.x * 256 + w * 32;
    {
        int cols4 = nCh * 2;  // 128 uint4 per row
        for (int idx = threadIdx.x; idx < 16 * cols4; idx += 256) {
            int r = idx / cols4, cc = idx % cols4;
            uint4 v = *reinterpret_cast<const uint4*>(A + (long long)r * 2048 + cc * 8);
            *reinterpret_cast<uint4*>(&s_a[r][cc * 8]) = v;
        }
    }
    __syncthreads();
    const uint4* bp0 = g_pFc + ((long long)(n0 >> 4) * nchTot) * 32 + lane;
    const uint4* bp1 = bp0 + (long long)nchTot * 32;
    uint32_t sab = (uint32_t)__cvta_generic_to_shared(&s_a[lane & 15][(lane >> 4) * 8]);
    float acc[4][4] = {{0.f}, {0.f}, {0.f}, {0.f}};
#pragma unroll 8
    for (int c = 0; c < nCh; c++) {
        uint4 b0 = __ldcs(bp0 + (long long)c * 32);
        uint4 b1 = __ldcs(bp1 + (long long)c * 32);
        uint32_t a0, a1, a2, a3;
        asm volatile("ldmatrix.sync.aligned.m8n8.x4.shared.b16 {%0,%1,%2,%3}, [%4];"
                     : "=r"(a0), "=r"(a1), "=r"(a2), "=r"(a3)
                     : "r"(sab + (uint32_t)c * 32));
        mma16816(acc[0], a0, a1, a2, a3, b0.x, b0.y);
        mma16816(acc[1], a0, a1, a2, a3, b0.z, b0.w);
        mma16816(acc[2], a0, a1, a2, a3, b1.x, b1.y);
        mma16816(acc[3], a0, a1, a2, a3, b1.z, b1.w);
    }
    int r0 = g, r1 = g + 8;
#pragma unroll
    for (int q = 0; q < 4; q++) {
        int col = n0 + q * 8 + tig * 2;
        float bv0 = bias[col], bv1 = bias[col + 1];
        C[(long long)r0 * (TT * VV) + col]     = acc[q][0] + bv0;
        C[(long long)r0 * (TT * VV) + col + 1] = acc[q][1] + bv1;
        C[(long long)r1 * (TT * VV) + col]     = acc[q][2] + bv0;
        C[(long long)r1 * (TT * VV) + col + 1] = acc[q][3] + bv1;
    }
}

// ---------------- in-place log_softmax over V (R14 single-kernel version) -----
__global__ __launch_bounds__(1024) void lsm_kernel(float* __restrict__ dout, int t) {
    float4* row = reinterpret_cast<float4*>(dout + (long long)blockIdx.x * TT * VV +
                                            (long long)t * VV);
    const int NV4 = VV / 4;
    __shared__ float sm[32];
    __shared__ float bc;
    int tid = threadIdx.x, lane = tid & 31, wid = tid >> 5;
    float m = -1e30f;
    for (int i = tid; i < NV4; i += 1024) {
        float4 v = row[i];
        m = fmaxf(m, fmaxf(fmaxf(v.x, v.y), fmaxf(v.z, v.w)));
    }
#pragma unroll
    for (int o = 16; o; o >>= 1) m = fmaxf(m, __shfl_xor_sync(0xffffffffu, m, o));
    if (!lane) sm[wid] = m;
    __syncthreads();
    if (tid < 32) {
        float mm = sm[tid];
#pragma unroll
        for (int o = 16; o; o >>= 1) mm = fmaxf(mm, __shfl_xor_sync(0xffffffffu, mm, o));
        if (!tid) bc = mm;
    }
    __syncthreads();
    m = bc;
    float s = 0.f;
    for (int i = tid; i < NV4; i += 1024) {
        float4 v = row[i];
        s += expf(v.x - m) + expf(v.y - m) + expf(v.z - m) + expf(v.w - m);
    }
#pragma unroll
    for (int o = 16; o; o >>= 1) s += __shfl_xor_sync(0xffffffffu, s, o);
    __syncthreads();
    if (!lane) sm[wid] = s;
    __syncthreads();
    if (tid < 32) {
        float ss = sm[tid];
#pragma unroll
        for (int o = 16; o; o >>= 1) ss += __shfl_xor_sync(0xffffffffu, ss, o);
        if (!tid) bc = m + logf(ss);
    }
    __syncthreads();
    float lse = bc;
    for (int i = tid; i < NV4; i += 1024) {
        float4 v = row[i];
        v.x -= lse; v.y -= lse; v.z -= lse; v.w -= lse;
        row[i] = v;
    }
}

// ---------------- host launch ----------------
extern "C" void kernel_launch(void* const* d_in, const int* in_sizes, int n_in,
                              void* d_out, int out_size) {
    const float* x    = (const float*)d_in[0];
    const int*   tseq = (const int*)d_in[1];
    const float* emb  = (const float*)d_in[2];
    const float* Wx   = (const float*)d_in[3];
    const float* Wh   = (const float*)d_in[4];
    const float* b1   = (const float*)d_in[5];
    const float* w2   = (const float*)d_in[6];
    const float* b2   = (const float*)d_in[7];
    const float* fcW  = (const float*)d_in[8];
    const float* fcb  = (const float*)d_in[9];
    const float* Wih0 = (const float*)d_in[10];
    const float* Whh0 = (const float*)d_in[11];
    const float* bih0 = (const float*)d_in[12];
    const float* bhh0 = (const float*)d_in[13];
    const float* Wih1 = (const float*)d_in[14];
    const float* Whh1 = (const float*)d_in[15];
    const float* bih1 = (const float*)d_in[16];
    const float* bhh1 = (const float*)d_in[17];
    const float* Wih2 = (const float*)d_in[18];
    const float* Whh2 = (const float*)d_in[19];
    const float* bih2 = (const float*)d_in[20];
    const float* bhh2 = (const float*)d_in[21];
    float* dout = (float*)d_out;

    static cudaStream_t s2 = nullptr, s3 = nullptr;
    static cudaEvent_t evA = nullptr, evB0 = nullptr, evB1 = nullptr;
    static cudaEvent_t evEnd2 = nullptr, evEnd3 = nullptr;
    if (!s2) {
        cudaStreamCreateWithFlags(&s2, cudaStreamNonBlocking);
        cudaStreamCreateWithFlags(&s3, cudaStreamNonBlocking);
        cudaEventCreateWithFlags(&evA, cudaEventDisableTiming);
        cudaEventCreateWithFlags(&evB0, cudaEventDisableTiming);
        cudaEventCreateWithFlags(&evB1, cudaEventDisableTiming);
        cudaEventCreateWithFlags(&evEnd2, cudaEventDisableTiming);
        cudaEventCreateWithFlags(&evEnd3, cudaEventDisableTiming);
    }

    // -------- prologue --------
    prolog_combined<<<36596, 256>>>(Wx, Wh, Wih0, Whh0, Wih1, Whh1, Wih2, Whh2, fcW,
                                    x, tseq, emb, w2);
    gemm_xproj<<<dim3(4, 128), 256>>>(b1);

    // -------- time loop: chain on stream0, fc on s2, lsm on s3 ------
    for (int t = 0; t < TT; t++) {
        if (t >= 2) cudaStreamWaitEvent(0, (t & 1) ? evB1 : evB0, 0);
        step_kernel<<<128, 256>>>(t, b2, bih0, bhh0, bih1, bhh1, bih2, bhh2, tseq, emb);
        cudaEventRecord(evA, 0);
        cudaStreamWaitEvent(s2, evA, 0);
        // fc(t): reads h2(t) = A2[(t+1)&1] + 1024 ; 125 blocks x 256 (R14 config)
        fc_gemm<<<125, 256, 0, s2>>>((t + 1) & 1, dout + (long long)t * VV, fcb);
        cudaEventRecord((t & 1) ? evB1 : evB0, s2);
        // lsm(t) on third stream: depends only on fc(t); overlaps fc(t+1)
        cudaStreamWaitEvent(s3, (t & 1) ? evB1 : evB0, 0);
        lsm_kernel<<<BB, 1024, 0, s3>>>(dout, t);
    }
    // join both side streams before capture ends
    cudaEventRecord(evEnd2, s2);
    cudaStreamWaitEvent(0, evEnd2, 0);
    cudaEventRecord(evEnd3, s3);
    cudaStreamWaitEvent(0, evEnd3, 0);
}